// round 4
// baseline (speedup 1.0000x reference)
#include <cuda_runtime.h>
#include <cstdint>

#define N_NODES 50000
#define F_IN    1024
#define F_HID   256
#define F_OUT   256
#define EPS     1e-5f
#define E_MAX   1048576
#define NB_SCAN 196        // ceil(50000/256)

// ---------------- scratch (allocation-free: device globals) ----------------
__device__ __align__(256) float g_h[(size_t)N_NODES * F_HID];    // GEMM outputs (h1, then h2)
__device__ __align__(256) float g_agg[(size_t)N_NODES * F_HID];  // aggregated layer-1 output
__device__ float g_deg[N_NODES];
__device__ float g_dinv[N_NODES];
__device__ int   g_cnt[N_NODES];       // in-degree (no self loop)
__device__ int   g_offs[N_NODES];      // CSR row start
__device__ int   g_cursor[N_NODES];    // fill cursors
__device__ int   g_chunk[256];         // per-chunk totals for scan
__device__ int   g_chunkbase[256];     // exclusive scan of chunk totals
__device__ int   g_csr_src[E_MAX];
__device__ float g_csr_w[E_MAX];
__device__ float g_colsum[F_OUT];
__device__ float g_colsumsq[F_OUT];

// ---------------- init / degree / histogram ----------------
__global__ void k_init() {
    int i = blockIdx.x * blockDim.x + threadIdx.x;
    if (i < N_NODES) { g_deg[i] = 1.0f; g_cnt[i] = 0; g_cursor[i] = 0; }
    if (i < F_OUT)   { g_colsum[i] = 0.f; g_colsumsq[i] = 0.f; }
}

// NOTE: edge_index is int32 on device (JAX x64 disabled downcasts int64).
__global__ void k_deg_hist(const int* __restrict__ ei,
                           const float* __restrict__ ew, int E) {
    int e = blockIdx.x * blockDim.x + threadIdx.x;
    if (e >= E) return;
    int d = ei[E + e];
    atomicAdd(&g_deg[d], ew[e]);
    atomicAdd(&g_cnt[d], 1);
}

__global__ void k_dinv() {
    int i = blockIdx.x * blockDim.x + threadIdx.x;
    if (i < N_NODES) g_dinv[i] = rsqrtf(g_deg[i]);  // deg >= 1 (self loop)
}

// ---------------- exclusive scan of g_cnt -> g_offs (3 kernels) ----------------
__global__ void k_scan1() {             // grid = NB_SCAN, 256 threads
    __shared__ int sm[256];
    int tid = threadIdx.x;
    int i = blockIdx.x * 256 + tid;
    int v = (i < N_NODES) ? g_cnt[i] : 0;
    sm[tid] = v;
    __syncthreads();
    for (int o = 1; o < 256; o <<= 1) {
        int t = (tid >= o) ? sm[tid - o] : 0;
        __syncthreads();
        sm[tid] += t;
        __syncthreads();
    }
    if (i < N_NODES) g_offs[i] = sm[tid] - v;       // exclusive within chunk
    if (tid == 255) g_chunk[blockIdx.x] = sm[tid];  // chunk total
}

__global__ void k_scan2() {             // 1 block, 256 threads
    __shared__ int sm[256];
    int tid = threadIdx.x;
    int v = (tid < NB_SCAN) ? g_chunk[tid] : 0;
    sm[tid] = v;
    __syncthreads();
    for (int o = 1; o < 256; o <<= 1) {
        int t = (tid >= o) ? sm[tid - o] : 0;
        __syncthreads();
        sm[tid] += t;
        __syncthreads();
    }
    if (tid < NB_SCAN) g_chunkbase[tid] = sm[tid] - v;
}

__global__ void k_scan3() {
    int i = blockIdx.x * blockDim.x + threadIdx.x;
    if (i < N_NODES) g_offs[i] += g_chunkbase[i >> 8];
}

// ---------------- CSR fill (by destination) ----------------
__global__ void k_fill(const int* __restrict__ ei,
                       const float* __restrict__ ew, int E) {
    int e = blockIdx.x * blockDim.x + threadIdx.x;
    if (e >= E) return;
    int s = ei[e];
    int d = ei[E + e];
    int slot = g_offs[d] + atomicAdd(&g_cursor[d], 1);
    g_csr_src[slot] = s;
    g_csr_w[slot] = g_dinv[s] * ew[e] * g_dinv[d];
}

// ---------------- fp32 SGEMM: C[M,N] = op(A)[M,K] @ B[K,N] ----------------
// Tile 128x128x8, 8x8 microtile, 256 threads.  FUSE: A-element -> relu(a + bias[k]).
template<bool FUSE>
__global__ __launch_bounds__(256) void k_sgemm(
    const float* __restrict__ A, const float* __restrict__ B,
    float* __restrict__ C, int M, int K, int N,
    const float* __restrict__ bias) {
    __shared__ float As[8][128];
    __shared__ float Bs[8][128];
    const int tid = threadIdx.x;
    const int bm = blockIdx.y * 128;
    const int bn = blockIdx.x * 128;

    const int a_row = tid >> 1;            // 0..127
    const int a_c4  = (tid & 1) << 2;      // 0 or 4
    const int b_row = tid >> 5;            // 0..7
    const int b_col = (tid & 31) << 2;     // 0..124

    const int tm = (tid >> 4) << 3;
    const int tn = (tid & 15) << 3;

    const int gm = bm + a_row;
    const float* Aptr = A + (size_t)gm * K + a_c4;
    const float* Bptr = B + (size_t)b_row * N + bn + b_col;

    float acc[8][8] = {};

    for (int k0 = 0; k0 < K; k0 += 8) {
        float4 av = make_float4(0.f, 0.f, 0.f, 0.f);
        if (gm < M) av = *reinterpret_cast<const float4*>(Aptr + k0);
        if (FUSE) {
            float4 bv = *reinterpret_cast<const float4*>(bias + k0 + a_c4);
            av.x = fmaxf(av.x + bv.x, 0.f);
            av.y = fmaxf(av.y + bv.y, 0.f);
            av.z = fmaxf(av.z + bv.z, 0.f);
            av.w = fmaxf(av.w + bv.w, 0.f);
        }
        As[a_c4 + 0][a_row] = av.x;
        As[a_c4 + 1][a_row] = av.y;
        As[a_c4 + 2][a_row] = av.z;
        As[a_c4 + 3][a_row] = av.w;
        *reinterpret_cast<float4*>(&Bs[b_row][b_col]) =
            *reinterpret_cast<const float4*>(Bptr + (size_t)k0 * N);
        __syncthreads();

        #pragma unroll
        for (int kk = 0; kk < 8; kk++) {
            float ar[8], br[8];
            #pragma unroll
            for (int i = 0; i < 8; i++) ar[i] = As[kk][tm + i];
            #pragma unroll
            for (int j = 0; j < 8; j++) br[j] = Bs[kk][tn + j];
            #pragma unroll
            for (int i = 0; i < 8; i++)
                #pragma unroll
                for (int j = 0; j < 8; j++)
                    acc[i][j] = fmaf(ar[i], br[j], acc[i][j]);
        }
        __syncthreads();
    }

    #pragma unroll
    for (int i = 0; i < 8; i++) {
        int row = bm + tm + i;
        if (row < M) {
            float* cp = C + (size_t)row * N + bn + tn;
            *reinterpret_cast<float4*>(cp)     = make_float4(acc[i][0], acc[i][1], acc[i][2], acc[i][3]);
            *reinterpret_cast<float4*>(cp + 4) = make_float4(acc[i][4], acc[i][5], acc[i][6], acc[i][7]);
        }
    }
}

// ---------------- CSR SpMM: warp per dst node, no atomics ----------------
// out[d,:] = dinv[d]^2 * h[d,:] + sum_{e: dst=d} w_e * h[src_e,:]
__global__ __launch_bounds__(256) void k_spmm(
    const float* __restrict__ h, float* __restrict__ out) {
    int node = blockIdx.x * 8 + (threadIdx.x >> 5);
    if (node >= N_NODES) return;
    int lane = threadIdx.x & 31;

    const float4* hrow = reinterpret_cast<const float4*>(h + (size_t)node * F_HID);
    float dd = g_dinv[node]; dd = dd * dd;
    float4 v0 = hrow[lane], v1 = hrow[lane + 32];
    float4 a0 = make_float4(v0.x * dd, v0.y * dd, v0.z * dd, v0.w * dd);
    float4 a1 = make_float4(v1.x * dd, v1.y * dd, v1.z * dd, v1.w * dd);

    int beg = g_offs[node];
    int end = beg + g_cnt[node];
    for (int k = beg; k < end; k++) {
        int s   = g_csr_src[k];
        float w = g_csr_w[k];
        const float4* sr = reinterpret_cast<const float4*>(h + (size_t)s * F_HID);
        float4 s0 = sr[lane], s1 = sr[lane + 32];
        a0.x = fmaf(w, s0.x, a0.x); a0.y = fmaf(w, s0.y, a0.y);
        a0.z = fmaf(w, s0.z, a0.z); a0.w = fmaf(w, s0.w, a0.w);
        a1.x = fmaf(w, s1.x, a1.x); a1.y = fmaf(w, s1.y, a1.y);
        a1.z = fmaf(w, s1.z, a1.z); a1.w = fmaf(w, s1.w, a1.w);
    }
    float4* op = reinterpret_cast<float4*>(out + (size_t)node * F_HID);
    op[lane]      = a0;
    op[lane + 32] = a1;
}

// ---------------- BatchNorm stats (over nodes), bias+relu fused ----------------
__global__ void k_bn_stats(const float* __restrict__ out, const float* __restrict__ b2) {
    int f = threadIdx.x;                    // 256 features
    int row0 = blockIdx.x * 64;
    float bias = b2[f];
    float s = 0.f, s2 = 0.f;
    for (int r = 0; r < 64; r++) {
        int row = row0 + r;
        if (row >= N_NODES) break;
        float v = fmaxf(out[(size_t)row * F_OUT + f] + bias, 0.f);
        s += v; s2 += v * v;
    }
    atomicAdd(&g_colsum[f], s);
    atomicAdd(&g_colsumsq[f], s2);
}

// ---------------- final: bias+relu -> BN -> LN, in place; warp per row ----------------
__global__ __launch_bounds__(256) void k_bn_ln(
    float* __restrict__ out, const float* __restrict__ b2,
    const float* __restrict__ bng, const float* __restrict__ bnb,
    const float* __restrict__ lng, const float* __restrict__ lnb) {
    int row  = (int)((blockIdx.x * 256u + threadIdx.x) >> 5);
    int lane = threadIdx.x & 31;
    if (row >= N_NODES) return;
    float* rowp = out + (size_t)row * F_OUT;
    const float invN = 1.0f / (float)N_NODES;
    float y[8];
    float s = 0.f, s2 = 0.f;
    #pragma unroll
    for (int j = 0; j < 8; j++) {
        int f = lane + 32 * j;
        float v   = fmaxf(rowp[f] + b2[f], 0.f);
        float mu  = g_colsum[f] * invN;
        float var = g_colsumsq[f] * invN - mu * mu;
        float yy  = (v - mu) * rsqrtf(var + EPS) * bng[f] + bnb[f];
        y[j] = yy;
        s += yy; s2 += yy * yy;
    }
    #pragma unroll
    for (int o = 16; o; o >>= 1) {
        s  += __shfl_xor_sync(0xffffffffu, s, o);
        s2 += __shfl_xor_sync(0xffffffffu, s2, o);
    }
    float m   = s * (1.0f / F_OUT);
    float var = s2 * (1.0f / F_OUT) - m * m;
    float r   = rsqrtf(var + EPS);
    #pragma unroll
    for (int j = 0; j < 8; j++) {
        int f = lane + 32 * j;
        rowp[f] = (y[j] - m) * r * lng[f] + lnb[f];
    }
}

// ---------------- launch ----------------
extern "C" void kernel_launch(void* const* d_in, const int* in_sizes, int n_in,
                              void* d_out, int out_size) {
    const float* x   = (const float*)d_in[0];
    const int*   ei  = (const int*)d_in[1];     // int32! (JAX x64 disabled)
    const float* ew  = (const float*)d_in[2];
    const float* W1  = (const float*)d_in[3];
    const float* b1  = (const float*)d_in[4];
    const float* W2  = (const float*)d_in[5];
    const float* b2  = (const float*)d_in[6];
    const float* bng = (const float*)d_in[7];
    const float* bnb = (const float*)d_in[8];
    const float* lng = (const float*)d_in[9];
    const float* lnb = (const float*)d_in[10];
    float* out = (float*)d_out;
    const int E = in_sizes[2];                  // edge_weight count = 800000

    float *hbuf, *abuf;
    cudaGetSymbolAddress((void**)&hbuf, g_h);
    cudaGetSymbolAddress((void**)&abuf, g_agg);

    const int T = 256;
    // graph prep: degrees, dinv, CSR-by-dst
    k_init<<<(N_NODES + T - 1) / T, T>>>();
    k_deg_hist<<<(E + T - 1) / T, T>>>(ei, ew, E);
    k_dinv<<<(N_NODES + T - 1) / T, T>>>();
    k_scan1<<<NB_SCAN, 256>>>();
    k_scan2<<<1, 256>>>();
    k_scan3<<<(N_NODES + T - 1) / T, T>>>();
    k_fill<<<(E + T - 1) / T, T>>>(ei, ew, E);

    // layer 1: h1 = x @ W1 ; agg1 = D^-1/2 (A+I) D^-1/2 h1
    {
        dim3 g(F_HID / 128, (N_NODES + 127) / 128);
        k_sgemm<false><<<g, 256>>>(x, W1, hbuf, N_NODES, F_IN, F_HID, nullptr);
    }
    k_spmm<<<(N_NODES + 7) / 8, 256>>>(hbuf, abuf);

    // layer 2: h2 = relu(agg1 + b1) @ W2 ; agg2 into d_out
    {
        dim3 g(F_OUT / 128, (N_NODES + 127) / 128);
        k_sgemm<true><<<g, 256>>>(abuf, W2, hbuf, N_NODES, F_HID, F_OUT, b1);
    }
    k_spmm<<<(N_NODES + 7) / 8, 256>>>(hbuf, out);

    // bias+relu fused into BN stats and finalize
    k_bn_stats<<<(N_NODES + 63) / 64, 256>>>(out, b2);
    k_bn_ln<<<(N_NODES + 7) / 8, 256>>>(out, b2, bng, bnb, lng, lnb);
}

// round 5
// speedup vs baseline: 2.5388x; 2.5388x over previous
#include <cuda_runtime.h>
#include <cstdint>

#define N_NODES 50000
#define F_IN    1024
#define F_HID   256
#define F_OUT   256
#define EPS     1e-5f
#define E_MAX   1048576
#define NB_SCAN 196        // ceil(50000/256)

// ---------------- scratch (allocation-free: device globals) ----------------
__device__ __align__(256) float g_h[(size_t)N_NODES * F_HID];    // GEMM outputs (h1, then h2)
__device__ __align__(256) float g_agg[(size_t)N_NODES * F_HID];  // aggregated layer-1 output
__device__ float g_deg[N_NODES];
__device__ float g_dinv[N_NODES];
__device__ int   g_cnt[N_NODES];
__device__ int   g_offs[N_NODES];
__device__ int   g_cursor[N_NODES];
__device__ int   g_chunk[256];
__device__ int   g_chunkbase[256];
__device__ int   g_csr_src[E_MAX];
__device__ float g_csr_w[E_MAX];
__device__ float g_colsum[F_OUT];
__device__ float g_colsumsq[F_OUT];

// ---------------- init / degree / histogram ----------------
__global__ void k_init() {
    int i = blockIdx.x * blockDim.x + threadIdx.x;
    if (i < N_NODES) { g_deg[i] = 1.0f; g_cnt[i] = 0; g_cursor[i] = 0; }
    if (i < F_OUT)   { g_colsum[i] = 0.f; g_colsumsq[i] = 0.f; }
}

// edge_index is int32 on device (JAX x64 disabled downcasts int64).
__global__ void k_deg_hist(const int* __restrict__ ei,
                           const float* __restrict__ ew, int E) {
    int e = blockIdx.x * blockDim.x + threadIdx.x;
    if (e >= E) return;
    int d = ei[E + e];
    atomicAdd(&g_deg[d], ew[e]);
    atomicAdd(&g_cnt[d], 1);
}

__global__ void k_dinv() {
    int i = blockIdx.x * blockDim.x + threadIdx.x;
    if (i < N_NODES) g_dinv[i] = rsqrtf(g_deg[i]);
}

// ---------------- exclusive scan of g_cnt -> g_offs ----------------
__global__ void k_scan1() {
    __shared__ int sm[256];
    int tid = threadIdx.x;
    int i = blockIdx.x * 256 + tid;
    int v = (i < N_NODES) ? g_cnt[i] : 0;
    sm[tid] = v;
    __syncthreads();
    for (int o = 1; o < 256; o <<= 1) {
        int t = (tid >= o) ? sm[tid - o] : 0;
        __syncthreads();
        sm[tid] += t;
        __syncthreads();
    }
    if (i < N_NODES) g_offs[i] = sm[tid] - v;
    if (tid == 255) g_chunk[blockIdx.x] = sm[tid];
}

__global__ void k_scan2() {
    __shared__ int sm[256];
    int tid = threadIdx.x;
    int v = (tid < NB_SCAN) ? g_chunk[tid] : 0;
    sm[tid] = v;
    __syncthreads();
    for (int o = 1; o < 256; o <<= 1) {
        int t = (tid >= o) ? sm[tid - o] : 0;
        __syncthreads();
        sm[tid] += t;
        __syncthreads();
    }
    if (tid < NB_SCAN) g_chunkbase[tid] = sm[tid] - v;
}

__global__ void k_scan3() {
    int i = blockIdx.x * blockDim.x + threadIdx.x;
    if (i < N_NODES) g_offs[i] += g_chunkbase[i >> 8];
}

// ---------------- CSR fill (by destination) ----------------
__global__ void k_fill(const int* __restrict__ ei,
                       const float* __restrict__ ew, int E) {
    int e = blockIdx.x * blockDim.x + threadIdx.x;
    if (e >= E) return;
    int s = ei[e];
    int d = ei[E + e];
    int slot = g_offs[d] + atomicAdd(&g_cursor[d], 1);
    g_csr_src[slot] = s;
    g_csr_w[slot] = g_dinv[s] * ew[e] * g_dinv[d];
}

// ---------------- tf32 tensor-core GEMM ----------------
// C[M,N] = A[M,K] @ B[K,N], row-major. BM=128, BN=128, BK=32, 256 threads.
// Warp grid 2(M) x 4(N); warp tile 64x32 via m16n8k8 (4 m-tiles x 4 n-tiles).
// cp.async double-buffered; cvt.rna on fragment load (unbiased tf32).

__device__ __forceinline__ uint32_t tf32of(float x) {
    uint32_t y;
    asm("cvt.rna.tf32.f32 %0, %1;" : "=r"(y) : "f"(x));
    return y;
}

__device__ __forceinline__ void mma_tf32(float* c, const uint32_t* a, const uint32_t* b) {
    asm volatile(
        "mma.sync.aligned.m16n8k8.row.col.f32.tf32.tf32.f32 "
        "{%0,%1,%2,%3}, {%4,%5,%6,%7}, {%8,%9}, {%0,%1,%2,%3};"
        : "+f"(c[0]), "+f"(c[1]), "+f"(c[2]), "+f"(c[3])
        : "r"(a[0]), "r"(a[1]), "r"(a[2]), "r"(a[3]), "r"(b[0]), "r"(b[1]));
}

__device__ __forceinline__ void cp_async16(uint32_t dst, const void* src, int src_sz) {
    asm volatile("cp.async.cg.shared.global [%0], [%1], 16, %2;"
                 :: "r"(dst), "l"(src), "r"(src_sz));
}

#define AS_PAD 36   // 36*4=144B row stride: 16B aligned, (4r+k)%32 conflict-free
#define BS_PAD 136  // 136*4=544B row stride: 16B aligned, (8k+c)%32 conflict-free

__global__ __launch_bounds__(256) void k_tf32gemm(
    const float* __restrict__ A, const float* __restrict__ B,
    float* __restrict__ C, int M, int K, int N) {
    __shared__ float As[2][128][AS_PAD];
    __shared__ float Bs[2][32][BS_PAD];

    const int tid  = threadIdx.x;
    const int bm   = blockIdx.y * 128;
    const int bn   = blockIdx.x * 128;
    const int warp = tid >> 5;
    const int lane = tid & 31;
    const int wm   = warp >> 2;        // 0..1
    const int wn   = warp & 3;         // 0..3
    const int g    = lane >> 2;        // 0..7
    const int q    = lane & 3;         // 0..3

    float c[4][4][4] = {};

    auto load_tiles = [&](int stage, int k0) {
        #pragma unroll
        for (int i = 0; i < 4; i++) {
            int idx = i * 256 + tid;               // 0..1023
            int row = idx >> 3;
            int c4  = (idx & 7) << 2;
            int grow = bm + row;
            int ok = (grow < M) ? 16 : 0;
            const float* src = A + (size_t)(ok ? grow : 0) * K + k0 + c4;
            cp_async16((uint32_t)__cvta_generic_to_shared(&As[stage][row][c4]), src, ok);
        }
        #pragma unroll
        for (int i = 0; i < 4; i++) {
            int idx = i * 256 + tid;
            int row = idx >> 5;                    // 0..31
            int c4  = (idx & 31) << 2;             // 0..124
            const float* src = B + (size_t)(k0 + row) * N + bn + c4;
            cp_async16((uint32_t)__cvta_generic_to_shared(&Bs[stage][row][c4]), src, 16);
        }
        asm volatile("cp.async.commit_group;");
    };

    const int nk = K >> 5;
    load_tiles(0, 0);
    asm volatile("cp.async.wait_group 0;");
    __syncthreads();

    int stage = 0;
    for (int kt = 0; kt < nk; kt++) {
        if (kt + 1 < nk) load_tiles(stage ^ 1, (kt + 1) << 5);

        #pragma unroll
        for (int s = 0; s < 4; s++) {
            const int k = s << 3;
            uint32_t af[4][4], bf[4][2];
            #pragma unroll
            for (int mt = 0; mt < 4; mt++) {
                int r0 = wm * 64 + mt * 16 + g;
                af[mt][0] = tf32of(As[stage][r0    ][k + q]);
                af[mt][1] = tf32of(As[stage][r0 + 8][k + q]);
                af[mt][2] = tf32of(As[stage][r0    ][k + q + 4]);
                af[mt][3] = tf32of(As[stage][r0 + 8][k + q + 4]);
            }
            #pragma unroll
            for (int nt = 0; nt < 4; nt++) {
                int c0 = wn * 32 + nt * 8 + g;
                bf[nt][0] = tf32of(Bs[stage][k + q    ][c0]);
                bf[nt][1] = tf32of(Bs[stage][k + q + 4][c0]);
            }
            #pragma unroll
            for (int mt = 0; mt < 4; mt++)
                #pragma unroll
                for (int nt = 0; nt < 4; nt++)
                    mma_tf32(c[mt][nt], af[mt], bf[nt]);
        }

        asm volatile("cp.async.wait_group 0;");
        __syncthreads();
        stage ^= 1;
    }

    #pragma unroll
    for (int mt = 0; mt < 4; mt++) {
        int row0 = bm + wm * 64 + mt * 16 + g;
        #pragma unroll
        for (int nt = 0; nt < 4; nt++) {
            int col = bn + wn * 32 + nt * 8 + 2 * q;
            if (row0 < M)
                *reinterpret_cast<float2*>(C + (size_t)row0 * N + col) =
                    make_float2(c[mt][nt][0], c[mt][nt][1]);
            if (row0 + 8 < M)
                *reinterpret_cast<float2*>(C + (size_t)(row0 + 8) * N + col) =
                    make_float2(c[mt][nt][2], c[mt][nt][3]);
        }
    }
}

// ---------------- CSR SpMM: warp per dst node, no atomics ----------------
// out[d,:] = dinv[d]^2 * h[d,:] + sum_e w_e * h[src_e,:]; optional relu(v + bias).
template<bool RELU>
__global__ __launch_bounds__(256) void k_spmm(
    const float* __restrict__ h, float* __restrict__ out,
    const float* __restrict__ bias) {
    int node = blockIdx.x * 8 + (threadIdx.x >> 5);
    if (node >= N_NODES) return;
    int lane = threadIdx.x & 31;

    const float4* hrow = reinterpret_cast<const float4*>(h + (size_t)node * F_HID);
    float dd = g_dinv[node]; dd = dd * dd;
    float4 v0 = hrow[lane], v1 = hrow[lane + 32];
    float4 a0 = make_float4(v0.x * dd, v0.y * dd, v0.z * dd, v0.w * dd);
    float4 a1 = make_float4(v1.x * dd, v1.y * dd, v1.z * dd, v1.w * dd);

    int beg = g_offs[node];
    int end = beg + g_cnt[node];
    for (int k = beg; k < end; k++) {
        int s   = g_csr_src[k];
        float w = g_csr_w[k];
        const float4* sr = reinterpret_cast<const float4*>(h + (size_t)s * F_HID);
        float4 s0 = sr[lane], s1 = sr[lane + 32];
        a0.x = fmaf(w, s0.x, a0.x); a0.y = fmaf(w, s0.y, a0.y);
        a0.z = fmaf(w, s0.z, a0.z); a0.w = fmaf(w, s0.w, a0.w);
        a1.x = fmaf(w, s1.x, a1.x); a1.y = fmaf(w, s1.y, a1.y);
        a1.z = fmaf(w, s1.z, a1.z); a1.w = fmaf(w, s1.w, a1.w);
    }
    if (RELU) {
        const float4* b4 = reinterpret_cast<const float4*>(bias);
        float4 bb0 = b4[lane], bb1 = b4[lane + 32];
        a0.x = fmaxf(a0.x + bb0.x, 0.f); a0.y = fmaxf(a0.y + bb0.y, 0.f);
        a0.z = fmaxf(a0.z + bb0.z, 0.f); a0.w = fmaxf(a0.w + bb0.w, 0.f);
        a1.x = fmaxf(a1.x + bb1.x, 0.f); a1.y = fmaxf(a1.y + bb1.y, 0.f);
        a1.z = fmaxf(a1.z + bb1.z, 0.f); a1.w = fmaxf(a1.w + bb1.w, 0.f);
    }
    float4* op = reinterpret_cast<float4*>(out + (size_t)node * F_HID);
    op[lane]      = a0;
    op[lane + 32] = a1;
}

// ---------------- BatchNorm stats (over nodes), bias+relu fused ----------------
__global__ void k_bn_stats(const float* __restrict__ out, const float* __restrict__ b2) {
    int f = threadIdx.x;
    int row0 = blockIdx.x * 64;
    float bias = b2[f];
    float s = 0.f, s2 = 0.f;
    for (int r = 0; r < 64; r++) {
        int row = row0 + r;
        if (row >= N_NODES) break;
        float v = fmaxf(out[(size_t)row * F_OUT + f] + bias, 0.f);
        s += v; s2 += v * v;
    }
    atomicAdd(&g_colsum[f], s);
    atomicAdd(&g_colsumsq[f], s2);
}

// ---------------- final: bias+relu -> BN -> LN, in place; warp per row ----------------
__global__ __launch_bounds__(256) void k_bn_ln(
    float* __restrict__ out, const float* __restrict__ b2,
    const float* __restrict__ bng, const float* __restrict__ bnb,
    const float* __restrict__ lng, const float* __restrict__ lnb) {
    int row  = (int)((blockIdx.x * 256u + threadIdx.x) >> 5);
    int lane = threadIdx.x & 31;
    if (row >= N_NODES) return;
    float* rowp = out + (size_t)row * F_OUT;
    const float invN = 1.0f / (float)N_NODES;
    float y[8];
    float s = 0.f, s2 = 0.f;
    #pragma unroll
    for (int j = 0; j < 8; j++) {
        int f = lane + 32 * j;
        float v   = fmaxf(rowp[f] + b2[f], 0.f);
        float mu  = g_colsum[f] * invN;
        float var = g_colsumsq[f] * invN - mu * mu;
        float yy  = (v - mu) * rsqrtf(var + EPS) * bng[f] + bnb[f];
        y[j] = yy;
        s += yy; s2 += yy * yy;
    }
    #pragma unroll
    for (int o = 16; o; o >>= 1) {
        s  += __shfl_xor_sync(0xffffffffu, s, o);
        s2 += __shfl_xor_sync(0xffffffffu, s2, o);
    }
    float m   = s * (1.0f / F_OUT);
    float var = s2 * (1.0f / F_OUT) - m * m;
    float r   = rsqrtf(var + EPS);
    #pragma unroll
    for (int j = 0; j < 8; j++) {
        int f = lane + 32 * j;
        rowp[f] = (y[j] - m) * r * lng[f] + lnb[f];
    }
}

// ---------------- launch ----------------
extern "C" void kernel_launch(void* const* d_in, const int* in_sizes, int n_in,
                              void* d_out, int out_size) {
    const float* x   = (const float*)d_in[0];
    const int*   ei  = (const int*)d_in[1];     // int32 (JAX x64 disabled)
    const float* ew  = (const float*)d_in[2];
    const float* W1  = (const float*)d_in[3];
    const float* b1  = (const float*)d_in[4];
    const float* W2  = (const float*)d_in[5];
    const float* b2  = (const float*)d_in[6];
    const float* bng = (const float*)d_in[7];
    const float* bnb = (const float*)d_in[8];
    const float* lng = (const float*)d_in[9];
    const float* lnb = (const float*)d_in[10];
    float* out = (float*)d_out;
    const int E = in_sizes[2];

    float *hbuf, *abuf;
    cudaGetSymbolAddress((void**)&hbuf, g_h);
    cudaGetSymbolAddress((void**)&abuf, g_agg);

    const int T = 256;
    // graph prep
    k_init<<<(N_NODES + T - 1) / T, T>>>();
    k_deg_hist<<<(E + T - 1) / T, T>>>(ei, ew, E);
    k_dinv<<<(N_NODES + T - 1) / T, T>>>();
    k_scan1<<<NB_SCAN, 256>>>();
    k_scan2<<<1, 256>>>();
    k_scan3<<<(N_NODES + T - 1) / T, T>>>();
    k_fill<<<(E + T - 1) / T, T>>>(ei, ew, E);

    // layer 1: h1 = x @ W1 ; agg1 = relu(D^-1/2 (A+I) D^-1/2 h1 + b1)
    {
        dim3 grid(F_HID / 128, (N_NODES + 127) / 128);
        k_tf32gemm<<<grid, 256>>>(x, W1, hbuf, N_NODES, F_IN, F_HID);
    }
    k_spmm<true><<<(N_NODES + 7) / 8, 256>>>(hbuf, abuf, b1);

    // layer 2: h2 = agg1 @ W2 ; agg2 into d_out (bias+relu deferred to BN stage)
    {
        dim3 grid(F_OUT / 128, (N_NODES + 127) / 128);
        k_tf32gemm<<<grid, 256>>>(abuf, W2, hbuf, N_NODES, F_HID, F_OUT);
    }
    k_spmm<false><<<(N_NODES + 7) / 8, 256>>>(hbuf, out, nullptr);

    // bias+relu fused into BN stats and finalize
    k_bn_stats<<<(N_NODES + 63) / 64, 256>>>(out, b2);
    k_bn_ln<<<(N_NODES + 7) / 8, 256>>>(out, b2, bng, bnb, lng, lnb);
}